// round 6
// baseline (speedup 1.0000x reference)
#include <cuda_runtime.h>
#include <cuda_bf16.h>
#include <math.h>
#include <cstdint>

#define Bz 64
#define Nn 196
#define Tt 32
#define Ss 31
#define VD 128
#define EM 256
#define AT 256
#define HD 512
#define VOC 30000
#define VOCP 30080
#define KX 384      // EM + VD
#define KG 896      // EM + VD + HD
#define JG 2048     // 4*HD
#define RTOT 1984   // Ss*Bz
#define RP 2048
#define K2 768      // split-concat K: A=[hi|hi|lo] x B=[hi|lo|hi]

typedef unsigned long long ULL;

// ---------------- scratch (device globals; zero-initialized, no allocation) ----------------
__device__ float g_UV[Bz*Nn*AT];
__device__ float g_h[2][Bz*HD];
__device__ float g_c[2][Bz*HD];
__device__ float g_ctx[Bz*VD];
__device__ float g_Wh[Bz*AT];
__device__ float g_H[Ss*Bz*HD];
__device__ float g_WwT[HD*AT];                 // Ww transposed [k][a]
__device__ float g_WgT[KG*JG];                 // [Wih|Whh] transposed [k][j]
__device__ float g_gb[JG];                     // bih + bhh
__device__ __nv_bfloat16 g_A2[RP*K2];          // E split-concat rows [hi|hi|lo]; pad rows stay 0
__device__ __nv_bfloat16 g_B2[VOCP*K2];        // embed split-concat rows [hi|lo|hi]; pad rows stay 0

// ---------------- packed f32x2 helpers ----------------
__device__ __forceinline__ ULL pack2(float x, float y){
    ULL r; asm("mov.b64 %0, {%1, %2};" : "=l"(r) : "f"(x), "f"(y)); return r;
}
__device__ __forceinline__ float2 unpack2(ULL v){
    float2 r; asm("mov.b64 {%0, %1}, %2;" : "=f"(r.x), "=f"(r.y) : "l"(v)); return r;
}
__device__ __forceinline__ void fma2(ULL& d, ULL a, ULL b){
    asm("fma.rn.f32x2 %0, %1, %2, %0;" : "+l"(d) : "l"(a), "l"(b));
}
__device__ __forceinline__ float sigf(float x){ return __fdividef(1.0f, 1.0f + __expf(-x)); }
__device__ __forceinline__ float tanha(float x){
    float r; asm("tanh.approx.f32 %0, %1;" : "=f"(r) : "f"(x)); return r;
}
__device__ __forceinline__ float tanhacc(float x){
    return __fdividef(2.0f, 1.0f + __expf(-2.0f*x)) - 1.0f;
}

// ---------------- mma.sync / ldmatrix / cp.async helpers ----------------
__device__ __forceinline__ uint32_t smem_to_u32(const void* smem_ptr){
    uint32_t addr;
    asm("{ .reg .u64 tmp; cvta.to.shared.u64 tmp, %1; cvt.u32.u64 %0, tmp; }"
        : "=r"(addr) : "l"(smem_ptr));
    return addr;
}
#define SWZ(o) ((o) ^ (((o) >> 3) & 0x70))

__device__ __forceinline__ void ldmatrix_x4(uint32_t& r0, uint32_t& r1, uint32_t& r2, uint32_t& r3,
                                            uint32_t addr){
    asm volatile("ldmatrix.sync.aligned.m8n8.x4.shared.b16 {%0,%1,%2,%3}, [%4];"
                 : "=r"(r0), "=r"(r1), "=r"(r2), "=r"(r3) : "r"(addr));
}
__device__ __forceinline__ void mma16816(float* d, const uint32_t* a, uint32_t b0, uint32_t b1){
    asm volatile("mma.sync.aligned.m16n8k16.row.col.f32.bf16.bf16.f32 "
                 "{%0,%1,%2,%3}, {%4,%5,%6,%7}, {%8,%9}, {%0,%1,%2,%3};"
                 : "+f"(d[0]), "+f"(d[1]), "+f"(d[2]), "+f"(d[3])
                 : "r"(a[0]), "r"(a[1]), "r"(a[2]), "r"(a[3]), "r"(b0), "r"(b1));
}
__device__ __forceinline__ void cp_async16(uint32_t dst, const void* src){
    asm volatile("cp.async.cg.shared.global [%0], [%1], 16;" :: "r"(dst), "l"(src) : "memory");
}

// ---------------- embed -> split-concat bf16 rows: B = [hi|lo|hi] ----------------
__global__ void __launch_bounds__(256) conv_embed_kernel(const float* __restrict__ embed){
    size_t i = ((size_t)blockIdx.x*256 + threadIdx.x)*4;
    size_t v = i / EM;
    int k = (int)(i % EM);
    float4 x = *(const float4*)(embed + i);
    float xs[4] = {x.x, x.y, x.z, x.w};
    unsigned short h[4], l[4];
    #pragma unroll
    for (int j = 0; j < 4; j++){
        __nv_bfloat16 hb = __float2bfloat16(xs[j]);
        float lo = xs[j] - __bfloat162float(hb);
        __nv_bfloat16 lb = __float2bfloat16(lo);
        h[j] = __bfloat16_as_ushort(hb);
        l[j] = __bfloat16_as_ushort(lb);
    }
    uint2 hv, lv;
    hv.x = (uint32_t)h[0] | ((uint32_t)h[1] << 16);
    hv.y = (uint32_t)h[2] | ((uint32_t)h[3] << 16);
    lv.x = (uint32_t)l[0] | ((uint32_t)l[1] << 16);
    lv.y = (uint32_t)l[2] | ((uint32_t)l[3] << 16);
    __nv_bfloat16* row = g_B2 + v*K2;
    *(uint2*)(row + k)       = hv;   // hi
    *(uint2*)(row + 256 + k) = lv;   // lo
    *(uint2*)(row + 512 + k) = hv;   // hi
}

// ---------------- one-shot prep: WgT + WwT transposes, biases, h0/c0 zero, Wh0 = Wb ----------------
// grid (64, 31), block (32, 8)
__global__ void prep_w_kernel(const float* __restrict__ Wih,
                              const float* __restrict__ Whh,
                              const float* __restrict__ Ww,
                              const float* __restrict__ Wb,
                              const float* __restrict__ bih,
                              const float* __restrict__ bhh){
    __shared__ float t[32][33];
    int bx = blockIdx.x, by = blockIdx.y;
    int tx = threadIdx.x, ty = threadIdx.y;
    if (by < 28){
        // WgT: [Wih|Whh] -> k-major [k][j]
        int j0 = bx*32, k0 = by*32;
        #pragma unroll
        for (int i = 0; i < 4; i++){
            int j = j0 + ty + i*8;
            int k = k0 + tx;
            float w = (k < KX) ? Wih[(size_t)j*KX + k] : Whh[(size_t)j*HD + (k - KX)];
            t[ty + i*8][tx] = w;
        }
        __syncthreads();
        #pragma unroll
        for (int i = 0; i < 4; i++)
            g_WgT[(size_t)(k0 + ty + i*8)*JG + j0 + tx] = t[tx][ty + i*8];
    } else if (by < 30){
        // WwT: Ww [a][k] -> [k][a]
        int a0 = (bx & 7)*32;
        int k0 = ((bx >> 3) + (by - 28)*8)*32;
        #pragma unroll
        for (int i = 0; i < 4; i++)
            t[ty + i*8][tx] = Ww[(size_t)(a0 + ty + i*8)*HD + k0 + tx];
        __syncthreads();
        #pragma unroll
        for (int i = 0; i < 4; i++)
            g_WwT[(size_t)(k0 + ty + i*8)*AT + a0 + tx] = t[tx][ty + i*8];
    } else {
        // misc: idx 0..16383
        int idx = bx*256 + ty*32 + tx;
        g_Wh[idx] = Wb[idx & 255];          // h0 = 0 -> Wh(step0) = Wb
        if (idx < JG) g_gb[idx] = bih[idx] + bhh[idx];
        g_h[0][idx] = 0.f;  g_h[0][idx + 16384] = 0.f;
        g_c[0][idx] = 0.f;  g_c[0][idx + 16384] = 0.f;
    }
}

// ---------------- UV ----------------
__global__ void __launch_bounds__(256) uv_kernel(const float* __restrict__ V,
                                                 const float* __restrict__ Uw,
                                                 const float* __restrict__ Ub){
    int b = blockIdx.x;
    int n0 = blockIdx.y * 32;
    int tid = threadIdx.x;
    __shared__ float sV[32][VD];
    for (int e = tid; e < 32*VD; e += 256){
        int n = n0 + (e / VD);
        sV[e / VD][e % VD] = (n < Nn) ? V[((size_t)b*Nn + n)*VD + (e % VD)] : 0.f;
    }
    __syncthreads();
    int a = tid;
    float acc[32];
    #pragma unroll
    for (int n = 0; n < 32; n++) acc[n] = 0.f;
    for (int kc = 0; kc < VD; kc += 16){
        float u[16];
        #pragma unroll
        for (int i = 0; i < 16; i += 4)
            *(float4*)&u[i] = *(const float4*)&Uw[a*VD + kc + i];
        #pragma unroll
        for (int n = 0; n < 32; n++){
            #pragma unroll
            for (int k = 0; k < 16; k++)
                acc[n] += u[k] * sV[n][kc + k];
        }
    }
    float ub = Ub[a];
    #pragma unroll
    for (int n = 0; n < 32; n++){
        int nn = n0 + n;
        if (nn < Nn) g_UV[((size_t)b*Nn + nn)*AT + a] = acc[n] + ub;
    }
}

// ---------------- Wh = h @ Ww.T + Wb : grid (4 b-tiles, 4 a-tiles), 256 thr ----------------
__global__ void __launch_bounds__(256) wh2_kernel(const float* __restrict__ Wb, int p){
    __shared__ __align__(16) float sH[2][16][68];
    __shared__ __align__(16) float sW[2][64][68];
    int tid = threadIdx.x;
    int b0 = blockIdx.x*16, a0 = blockIdx.y*64;
    const float* hp = g_h[p];
    int bq = tid >> 4, aq = tid & 15;
    ULL acc0 = 0ull, acc1 = 0ull;
    float4 rh, rw[4];

#define WH_LOADC(kc) { \
    rh = *(const float4*)&hp[(size_t)(b0 + (tid>>4))*HD + (kc) + (tid&15)*4]; \
    _Pragma("unroll") \
    for (int i = 0; i < 4; i++) \
        rw[i] = *(const float4*)&g_WwT[(size_t)((kc) + (tid>>4) + i*16)*AT + a0 + (tid&15)*4]; \
}
#define WH_STOREC(buf) { \
    *(float4*)&sH[buf][tid>>4][(tid&15)*4] = rh; \
    _Pragma("unroll") \
    for (int i = 0; i < 4; i++) \
        *(float4*)&sW[buf][(tid>>4) + i*16][(tid&15)*4] = rw[i]; \
}

    WH_LOADC(0);
    WH_STOREC(0);
    __syncthreads();
    for (int c = 0; c < 8; c++){
        int buf = c & 1;
        if (c < 7) WH_LOADC((c + 1)*64);
        #pragma unroll
        for (int k = 0; k < 64; k++){
            float av = sH[buf][bq][k];
            ULL a2 = pack2(av, av);
            ulonglong2 w = *(const ulonglong2*)&sW[buf][k][aq*4];
            fma2(acc0, a2, w.x);
            fma2(acc1, a2, w.y);
        }
        if (c < 7) WH_STOREC(buf ^ 1);
        __syncthreads();
    }
    int b = b0 + bq, a = a0 + aq*4;
    float4 wb = *(const float4*)&Wb[a];
    float2 p0 = unpack2(acc0), p1 = unpack2(acc1);
    float4 o = {p0.x + wb.x, p0.y + wb.y, p1.x + wb.z, p1.y + wb.w};
    *(float4*)&g_Wh[b*AT + a] = o;
#undef WH_LOADC
#undef WH_STOREC
}

// ---------------- attention: e + softmax + ctx. grid 64, 1024 thr ----------------
__global__ void __launch_bounds__(1024) attn_kernel(const float* __restrict__ vw,
                                                    const float* __restrict__ vb,
                                                    const float* __restrict__ V){
    __shared__ float sWh[AT];
    __shared__ float sv[AT];
    __shared__ float se[Nn];
    __shared__ float sred[32];
    __shared__ float s_sc[2];
    __shared__ __align__(16) float4 sc4[32][32];

    int b = blockIdx.x, tid = threadIdx.x;
    int warp = tid >> 5, lane = tid & 31;
    if (tid < AT){ sWh[tid] = g_Wh[b*AT + tid]; sv[tid] = vw[tid]; }
    __syncthreads();

    // e_n = v . tanh(Wh + UV[n]) + vb  — 32 warps over n
    float vbias = vb[0];
    for (int n = warp; n < Nn; n += 32){
        const float* uvp = g_UV + ((size_t)b*Nn + n)*AT;
        float pz = 0.f;
        #pragma unroll
        for (int j = 0; j < 8; j++){
            int aa = lane + j*32;
            pz += tanha(sWh[aa] + uvp[aa]) * sv[aa];
        }
        #pragma unroll
        for (int o = 16; o; o >>= 1) pz += __shfl_xor_sync(0xffffffffu, pz, o);
        if (lane == 0) se[n] = pz + vbias;
    }
    __syncthreads();

    // softmax max
    float m = (tid < Nn) ? se[tid] : -1e30f;
    #pragma unroll
    for (int o = 16; o; o >>= 1) m = fmaxf(m, __shfl_xor_sync(0xffffffffu, m, o));
    if (lane == 0) sred[warp] = m;
    __syncthreads();
    if (tid == 0){
        float mm = sred[0];
        #pragma unroll
        for (int i = 1; i < 32; i++) mm = fmaxf(mm, sred[i]);
        s_sc[0] = mm;
    }
    __syncthreads();
    float mm = s_sc[0];
    float ex = (tid < Nn) ? __expf(se[tid] - mm) : 0.f;
    if (tid < Nn) se[tid] = ex;
    float sum = ex;
    #pragma unroll
    for (int o = 16; o; o >>= 1) sum += __shfl_xor_sync(0xffffffffu, sum, o);
    if (lane == 0) sred[warp] = sum;
    __syncthreads();
    if (tid == 0){
        float s = 0.f;
        #pragma unroll
        for (int i = 0; i < 32; i++) s += sred[i];
        s_sc[1] = 1.0f / s;
    }
    __syncthreads();

    // ctx: 32 n-groups x 32 d-quads
    float4 a4 = {0.f, 0.f, 0.f, 0.f};
    for (int n = warp; n < Nn; n += 32){
        float w = se[n];
        float4 v = *(const float4*)&V[((size_t)b*Nn + n)*VD + lane*4];
        a4.x += w*v.x; a4.y += w*v.y; a4.z += w*v.z; a4.w += w*v.w;
    }
    sc4[warp][lane] = a4;
    __syncthreads();
    #pragma unroll
    for (int off = 16; off; off >>= 1){
        if (warp < off){
            float4 x = sc4[warp][lane], y4 = sc4[warp + off][lane];
            x.x += y4.x; x.y += y4.y; x.z += y4.z; x.w += y4.w;
            sc4[warp][lane] = x;
        }
        __syncthreads();
    }
    if (tid < 32){
        float inv = s_sc[1];
        float4 cv = sc4[0][tid];
        cv.x *= inv; cv.y *= inv; cv.z *= inv; cv.w *= inv;
        *(float4*)&g_ctx[b*VD + tid*4] = cv;
    }
}

// ---------------- LSTM step (gathers embed rows directly) ----------------
__global__ void __launch_bounds__(256) lstm_kernel(const int* __restrict__ y,
                                                   const float* __restrict__ embed,
                                                   int step, int p){
    __shared__ float sA[2][32][68];
    __shared__ float sWt[2][64][36];
    __shared__ float sG[32][32];
    __shared__ int stok[32];

    int tid = threadIdx.x;
    int b0 = blockIdx.x*32;
    int u0 = blockIdx.y*8;
    const float* hp = g_h[p];

    if (tid < 32) stok[tid] = y[(b0 + tid)*Tt + step];
    __syncthreads();

    int bt = tid >> 3;
    int jt = tid & 7;
    ULL acc0 = 0ull, acc1 = 0ull;
    float ra[8], rw[8];

#define LSTM_LOADC(kc) { \
    _Pragma("unroll") \
    for (int it = 0; it < 8; it++){ \
        int f = tid + it*256; \
        int b_l = f >> 6, kk = f & 63; \
        int k = (kc) + kk, bb = b0 + b_l; \
        float v; \
        if (k < EM)      v = embed[(size_t)stok[b_l]*EM + k]; \
        else if (k < KX) v = g_ctx[bb*VD + (k - EM)]; \
        else             v = hp[bb*HD + (k - KX)]; \
        ra[it] = v; \
        int k2 = f >> 5, lr = f & 31; \
        rw[it] = g_WgT[(size_t)((kc) + k2)*JG + (lr >> 3)*HD + u0 + (lr & 7)]; \
    } }

#define LSTM_STOREC(buf) { \
    _Pragma("unroll") \
    for (int it = 0; it < 8; it++){ \
        int f = tid + it*256; \
        sA[buf][f >> 6][f & 63] = ra[it]; \
        sWt[buf][f >> 5][f & 31] = rw[it]; \
    } }

    LSTM_LOADC(0);
    LSTM_STOREC(0);
    __syncthreads();

    for (int c = 0; c < 14; c++){
        int buf = c & 1;
        if (c < 13) LSTM_LOADC((c + 1)*64);
        #pragma unroll
        for (int k = 0; k < 64; k += 4){
            float4 av = *(const float4*)&sA[buf][bt][k];
            ulonglong2 w0 = *(const ulonglong2*)&sWt[buf][k  ][jt*4];
            ulonglong2 w1 = *(const ulonglong2*)&sWt[buf][k+1][jt*4];
            ulonglong2 w2 = *(const ulonglong2*)&sWt[buf][k+2][jt*4];
            ulonglong2 w3 = *(const ulonglong2*)&sWt[buf][k+3][jt*4];
            ULL a0 = pack2(av.x, av.x), a1 = pack2(av.y, av.y);
            ULL a2 = pack2(av.z, av.z), a3 = pack2(av.w, av.w);
            fma2(acc0, a0, w0.x); fma2(acc1, a0, w0.y);
            fma2(acc0, a1, w1.x); fma2(acc1, a1, w1.y);
            fma2(acc0, a2, w2.x); fma2(acc1, a2, w2.y);
            fma2(acc0, a3, w3.x); fma2(acc1, a3, w3.y);
        }
        if (c < 13) LSTM_STOREC(buf ^ 1);
        __syncthreads();
    }

    float2 v01 = unpack2(acc0), v23 = unpack2(acc1);
    sG[bt][jt*4 + 0] = v01.x;
    sG[bt][jt*4 + 1] = v01.y;
    sG[bt][jt*4 + 2] = v23.x;
    sG[bt][jt*4 + 3] = v23.y;
    __syncthreads();

    int b_l = tid >> 3, uu = tid & 7;
    int bb = b0 + b_l, u = u0 + uu;
    float iv = sG[b_l][ 0 + uu] + g_gb[u];
    float fv = sG[b_l][ 8 + uu] + g_gb[HD + u];
    float gv = sG[b_l][16 + uu] + g_gb[2*HD + u];
    float ov = sG[b_l][24 + uu] + g_gb[3*HD + u];
    float cp = g_c[p][bb*HD + u];
    float cn = sigf(fv)*cp + sigf(iv)*tanhacc(gv);
    float hn = sigf(ov)*tanhacc(cn);
    int q = p ^ 1;
    g_c[q][bb*HD + u] = cn;
    g_h[q][bb*HD + u] = hn;
    g_H[((size_t)step*Bz + bb)*HD + u] = hn;
#undef LSTM_LOADC
#undef LSTM_STOREC
}

// ---------------- proj: E = H @ proj.T, epilogue writes split-concat rows A = [hi|hi|lo] ----------------
__global__ void __launch_bounds__(256) proj_kernel(const float* __restrict__ projw){
    __shared__ float sA[64][33];
    __shared__ float sW[64][33];
    int tid = threadIdx.x;
    int r0 = blockIdx.x*64, a0 = blockIdx.y*64;
    int tx = tid & 15, ty = tid >> 4;
    float acc[4][4] = {};
    for (int kc = 0; kc < HD; kc += 32){
        for (int e = tid; e < 64*32; e += 256){
            int row = e >> 5, col = e & 31;
            sA[row][col] = g_H[(size_t)(r0 + row)*HD + kc + col];
            sW[row][col] = projw[(size_t)(a0 + row)*HD + kc + col];
        }
        __syncthreads();
        #pragma unroll
        for (int k = 0; k < 32; k++){
            float af[4], wf[4];
            #pragma unroll
            for (int i = 0; i < 4; i++) af[i] = sA[ty*4 + i][k];
            #pragma unroll
            for (int j = 0; j < 4; j++) wf[j] = sW[tx*4 + j][k];
            #pragma unroll
            for (int i = 0; i < 4; i++)
                #pragma unroll
                for (int j = 0; j < 4; j++)
                    acc[i][j] += af[i]*wf[j];
        }
        __syncthreads();
    }
    #pragma unroll
    for (int i = 0; i < 4; i++){
        int r = r0 + ty*4 + i;
        __nv_bfloat16* row = g_A2 + (size_t)r*K2;
        #pragma unroll
        for (int jp = 0; jp < 2; jp++){
            float x0 = acc[i][jp*2], x1 = acc[i][jp*2 + 1];
            __nv_bfloat16 h0 = __float2bfloat16(x0);
            __nv_bfloat16 h1 = __float2bfloat16(x1);
            __nv_bfloat16 l0 = __float2bfloat16(x0 - __bfloat162float(h0));
            __nv_bfloat16 l1 = __float2bfloat16(x1 - __bfloat162float(h1));
            uint32_t hv = (uint32_t)__bfloat16_as_ushort(h0) | ((uint32_t)__bfloat16_as_ushort(h1) << 16);
            uint32_t lv = (uint32_t)__bfloat16_as_ushort(l0) | ((uint32_t)__bfloat16_as_ushort(l1) << 16);
            int k = a0 + tx*4 + jp*2;
            *(uint32_t*)(row + k)       = hv;   // hi (pairs with B hi)
            *(uint32_t*)(row + 256 + k) = hv;   // hi (pairs with B lo)
            *(uint32_t*)(row + 512 + k) = lv;   // lo (pairs with B hi)
        }
    }
}

// ---------------- logits: mma.sync bf16 GEMM, K=768, 128x128 tile, cp.async 3-stage ----------------
#define KCH 64
#define STG_BYTES 32768
#define LOGIT_SMEM (3*STG_BYTES)

extern __shared__ char lg_smem[];

__global__ void __launch_bounds__(256, 2) logit_mma_kernel(float* __restrict__ out){
    uint32_t sb = smem_to_u32(lg_smem);
    int tid = threadIdx.x;
    int warp = tid >> 5, lane = tid & 31;
    int wm = warp >> 2, wn = warp & 3;
    int r0 = blockIdx.x*128, v0 = blockIdx.y*128;
    const __nv_bfloat16* Ag = g_A2 + (size_t)r0*K2;
    const __nv_bfloat16* Bg = g_B2 + (size_t)v0*K2;

    float acc[4][4][4];
    #pragma unroll
    for (int i = 0; i < 4; i++)
        #pragma unroll
        for (int j = 0; j < 4; j++)
            #pragma unroll
            for (int q = 0; q < 4; q++) acc[i][j][q] = 0.f;

#define LOAD_STAGE(s, kc) { \
    uint32_t base_ = sb + (uint32_t)(s)*STG_BYTES; \
    _Pragma("unroll") \
    for (int it = 0; it < 8; it++){ \
        int f = tid + it*256; \
        int side = f >> 10, idx = f & 1023; \
        int row = idx >> 3, ch = idx & 7; \
        const __nv_bfloat16* src = (side ? Bg : Ag) + (size_t)row*K2 + (kc) + ch*8; \
        uint32_t off = (uint32_t)(side*16384 + SWZ(row*128 + ch*16)); \
        cp_async16(base_ + off, src); \
    } \
    asm volatile("cp.async.commit_group;" ::: "memory"); \
}

    LOAD_STAGE(0, 0);
    LOAD_STAGE(1, KCH);
    LOAD_STAGE(2, 2*KCH);

    int lrow = ((lane >> 3) & 1)*8 + (lane & 7);
    int lkb  = (lane >> 4)*16;

    for (int c = 0; c < 12; c++){
        asm volatile("cp.async.wait_group 2;" ::: "memory");
        __syncthreads();
        int s = c % 3;
        uint32_t aBase = sb + (uint32_t)s*STG_BYTES;
        uint32_t bBase = aBase + 16384;
        #pragma unroll
        for (int k16 = 0; k16 < 4; k16++){
            int kb = k16*32 + lkb;
            uint32_t a[4][4], bfr[2][4];
            #pragma unroll
            for (int mi = 0; mi < 4; mi++){
                int row = wm*64 + mi*16 + lrow;
                ldmatrix_x4(a[mi][0], a[mi][1], a[mi][2], a[mi][3],
                            aBase + (uint32_t)SWZ(row*128 + kb));
            }
            #pragma unroll
            for (int nh = 0; nh < 2; nh++){
                int row = wn*32 + nh*16 + lrow;
                ldmatrix_x4(bfr[nh][0], bfr[nh][1], bfr[nh][2], bfr[nh][3],
                            bBase + (uint32_t)SWZ(row*128 + kb));
            }
            #pragma unroll
            for (int mi = 0; mi < 4; mi++)
                #pragma unroll
                for (int nj = 0; nj < 4; nj++)
                    mma16816(acc[mi][nj], a[mi], bfr[nj>>1][nj&1], bfr[nj>>1][(nj&1)+2]);
        }
        __syncthreads();
        if (c + 3 < 12){
            LOAD_STAGE((c + 3) % 3, (c + 3)*KCH);
        } else {
            asm volatile("cp.async.commit_group;" ::: "memory");
        }
    }

    #pragma unroll
    for (int mi = 0; mi < 4; mi++){
        int rbase = r0 + wm*64 + mi*16 + (lane >> 2);
        #pragma unroll
        for (int half = 0; half < 2; half++){
            int r = rbase + half*8;
            if (r < RTOT){
                int st = r >> 6, bb = r & 63;
                float* op = out + ((size_t)bb*Ss + st)*VOC;
                #pragma unroll
                for (int nj = 0; nj < 4; nj++){
                    int v = v0 + wn*32 + nj*8 + (lane & 3)*2;
                    if (v < VOC){
                        float2 val = {acc[mi][nj][half*2], acc[mi][nj][half*2 + 1]};
                        *(float2*)(op + v) = val;
                    }
                }
            }
        }
    }
#undef LOAD_STAGE
}

// ---------------- launch ----------------
extern "C" void kernel_launch(void* const* d_in, const int* in_sizes, int n_in,
                              void* d_out, int out_size){
    const float* V     = (const float*)d_in[0];
    const int*   y     = (const int*)  d_in[1];
    const float* embed = (const float*)d_in[2];
    const float* Ww    = (const float*)d_in[3];
    const float* Wb    = (const float*)d_in[4];
    const float* Uw    = (const float*)d_in[5];
    const float* Ub    = (const float*)d_in[6];
    const float* vw    = (const float*)d_in[7];
    const float* vb    = (const float*)d_in[8];
    const float* Wih   = (const float*)d_in[9];
    const float* Whh   = (const float*)d_in[10];
    const float* bih   = (const float*)d_in[11];
    const float* bhh   = (const float*)d_in[12];
    const float* projw = (const float*)d_in[13];
    float* out = (float*)d_out;

    cudaFuncSetAttribute(logit_mma_kernel,
                         cudaFuncAttributeMaxDynamicSharedMemorySize, LOGIT_SMEM);

    // order: lstm_kernel is launch #4 (ncu profiles #4)
    uv_kernel<<<dim3(Bz, 7), 256>>>(V, Uw, Ub);                                  // 1
    prep_w_kernel<<<dim3(64, 31), dim3(32, 8)>>>(Wih, Whh, Ww, Wb, bih, bhh);    // 2
    attn_kernel<<<Bz, 1024>>>(vw, vb, V);                                        // 3 (step 0; Wh=Wb)
    lstm_kernel<<<dim3(2, 64), 256>>>(y, embed, 0, 0);                           // 4 <- profiled
    conv_embed_kernel<<<(VOC*EM)/(256*4), 256>>>(embed);                         // 5

    for (int j = 1; j < Ss; j++){
        int p = j & 1;
        wh2_kernel<<<dim3(4, 4), 256>>>(Wb, p);
        attn_kernel<<<Bz, 1024>>>(vw, vb, V);
        lstm_kernel<<<dim3(2, 64), 256>>>(y, embed, j, p);
    }

    proj_kernel<<<dim3(Ss, 4), 256>>>(projw);
    logit_mma_kernel<<<dim3(RP/128, VOCP/128), 256, LOGIT_SMEM>>>(out);
}